// round 5
// baseline (speedup 1.0000x reference)
#include <cuda_runtime.h>
#include <cstdint>

// Problem constants (fixed by reference: B=32, S=2048, D=512)
#define PB 32
#define PS 2048
#define D4 128              // float4 per (b,s) position

// Scratch: rank per (b,s). rank >= 0 iff mask set; -1 otherwise.
__device__ int g_rank[PB * PS];

// ---------------------------------------------------------------------------
// Kernel 1: per-row inclusive scan of the mask (int32) -> ranks.
// One block (1024 threads) per row; each thread handles 2 consecutive ints.
// ---------------------------------------------------------------------------
__global__ void __launch_bounds__(1024, 1)
rank_scan_kernel(const int* __restrict__ masks)
{
    const int b = blockIdx.x;
    const int* m = masks + (size_t)b * PS;
    const int t = threadIdx.x;
    const int lane = t & 31;
    const int warp = t >> 5;

    const int i0 = 2 * t;
    const int2 mv = *reinterpret_cast<const int2*>(m + i0);
    const int m0 = (mv.x != 0) ? 1 : 0;
    const int m1 = (mv.y != 0) ? 1 : 0;
    const int s = m0 + m1;

    int incl = s;
    #pragma unroll
    for (int off = 1; off < 32; off <<= 1) {
        int v = __shfl_up_sync(0xFFFFFFFFu, incl, off);
        if (lane >= off) incl += v;
    }

    __shared__ int warp_tot[32];
    if (lane == 31) warp_tot[warp] = incl;
    __syncthreads();

    if (warp == 0) {
        int v = warp_tot[lane];
        int wincl = v;
        #pragma unroll
        for (int off = 1; off < 32; off <<= 1) {
            int u = __shfl_up_sync(0xFFFFFFFFu, wincl, off);
            if (lane >= off) wincl += u;
        }
        warp_tot[lane] = wincl - v;   // exclusive warp base
    }
    __syncthreads();

    const int base = warp_tot[warp];
    const int excl_thread = base + (incl - s);

    const int c0 = excl_thread + m0;
    const int c1 = c0 + m1;

    int2 rv;
    rv.x = m0 ? (c0 - 1) : -1;
    rv.y = m1 ? (c1 - 1) : -1;
    *reinterpret_cast<int2*>(g_rank + (size_t)b * PS + i0) = rv;
}

// ---------------------------------------------------------------------------
// Kernel 2: out = seqs + (rank >= 0 ? pe[rank] : 0).
// 4 float4 per thread, all loads front-batched for maximum per-warp MLP.
// Streaming hints (__ldcs/__stcs) keep seqs/out from evicting pe in L2.
// ---------------------------------------------------------------------------
__global__ void __launch_bounds__(256)
pe_add_kernel(const float4* __restrict__ seqs,
              const float4* __restrict__ pe,
              float4*       __restrict__ out)
{
    const unsigned t    = threadIdx.x;
    const unsigned base = blockIdx.x * 1024u + t;   // 4 * 256 per block

    unsigned idx[4];
    int      r[4];
    float4   v[4];

    #pragma unroll
    for (int k = 0; k < 4; k++) idx[k] = base + (unsigned)k * 256u;

    // Front-batch: 4 rank loads + 4 seq loads issued before any dependent use
    #pragma unroll
    for (int k = 0; k < 4; k++) r[k] = __ldg(&g_rank[idx[k] >> 7]);
    #pragma unroll
    for (int k = 0; k < 4; k++) v[k] = __ldcs(seqs + idx[k]);

    #pragma unroll
    for (int k = 0; k < 4; k++) {
        if (r[k] >= 0) {
            const float4 p = __ldg(pe + (unsigned)r[k] * D4 + (idx[k] & 127u));
            v[k].x += p.x; v[k].y += p.y; v[k].z += p.z; v[k].w += p.w;
        }
    }

    #pragma unroll
    for (int k = 0; k < 4; k++) __stcs(out + idx[k], v[k]);
}

// ---------------------------------------------------------------------------
// Launch.
// Inputs (metadata order): seqs [B,S,D] f32, masks [B,S] int32, pe [2048,D] f32
// Output: [B,S,D] f32
// ---------------------------------------------------------------------------
extern "C" void kernel_launch(void* const* d_in, const int* in_sizes, int n_in,
                              void* d_out, int out_size)
{
    const float* seqs  = (const float*)d_in[0];
    const int*   masks = (const int*)d_in[1];
    const float* pe    = (const float*)d_in[2];
    float*       out   = (float*)d_out;

    (void)in_sizes; (void)n_in; (void)out_size;

    rank_scan_kernel<<<PB, 1024>>>(masks);

    const unsigned total4 = (unsigned)PB * PS * D4;   // 8,388,608
    pe_add_kernel<<<total4 / 1024, 256>>>(
        (const float4*)seqs, (const float4*)pe, (float4*)out);
}

// round 6
// speedup vs baseline: 1.0063x; 1.0063x over previous
#include <cuda_runtime.h>
#include <cstdint>

// Problem constants (fixed by reference: B=32, S=2048, D=512)
#define PB 32
#define PS 2048
#define D4 128              // float4 per (b,s) position

// Scratch: rank per (b,s). rank >= 0 iff mask set; -1 otherwise.
__device__ int g_rank[PB * PS];

// ---------------------------------------------------------------------------
// Kernel 1: per-row inclusive scan of the mask (int32) -> ranks.
// One block (1024 threads) per row; each thread handles 2 consecutive ints.
// ---------------------------------------------------------------------------
__global__ void __launch_bounds__(1024, 1)
rank_scan_kernel(const int* __restrict__ masks)
{
    const int b = blockIdx.x;
    const int* m = masks + (size_t)b * PS;
    const int t = threadIdx.x;
    const int lane = t & 31;
    const int warp = t >> 5;

    const int i0 = 2 * t;
    const int2 mv = *reinterpret_cast<const int2*>(m + i0);
    const int m0 = (mv.x != 0) ? 1 : 0;
    const int m1 = (mv.y != 0) ? 1 : 0;
    const int s = m0 + m1;

    int incl = s;
    #pragma unroll
    for (int off = 1; off < 32; off <<= 1) {
        int v = __shfl_up_sync(0xFFFFFFFFu, incl, off);
        if (lane >= off) incl += v;
    }

    __shared__ int warp_tot[32];
    if (lane == 31) warp_tot[warp] = incl;
    __syncthreads();

    if (warp == 0) {
        int v = warp_tot[lane];
        int wincl = v;
        #pragma unroll
        for (int off = 1; off < 32; off <<= 1) {
            int u = __shfl_up_sync(0xFFFFFFFFu, wincl, off);
            if (lane >= off) wincl += u;
        }
        warp_tot[lane] = wincl - v;   // exclusive warp base
    }
    __syncthreads();

    const int base = warp_tot[warp];
    const int excl_thread = base + (incl - s);

    const int c0 = excl_thread + m0;
    const int c1 = c0 + m1;

    int2 rv;
    rv.x = m0 ? (c0 - 1) : -1;
    rv.y = m1 ? (c1 - 1) : -1;
    *reinterpret_cast<int2*>(g_rank + (size_t)b * PS + i0) = rv;
}

// ---------------------------------------------------------------------------
// Kernel 2: out = seqs + (rank >= 0 ? pe[rank] : 0).
// 512 threads/block, 2 float4 per thread, front-batched loads.
// Streaming hints (__ldcs/__stcs) keep seqs/out from evicting pe in L2.
// Each warp covers 32 consecutive float4 of one row -> rank load is a
// warp-uniform broadcast.
// ---------------------------------------------------------------------------
__global__ void __launch_bounds__(512)
pe_add_kernel(const float4* __restrict__ seqs,
              const float4* __restrict__ pe,
              float4*       __restrict__ out)
{
    const unsigned t    = threadIdx.x;
    const unsigned idx0 = blockIdx.x * 1024u + t;   // element 0
    const unsigned idx1 = idx0 + 512u;              // element 1

    // Front-batch all independent loads
    const int r0 = __ldg(&g_rank[idx0 >> 7]);
    const int r1 = __ldg(&g_rank[idx1 >> 7]);
    float4 v0 = __ldcs(seqs + idx0);
    float4 v1 = __ldcs(seqs + idx1);

    if (r0 >= 0) {
        const float4 p = __ldg(pe + (unsigned)r0 * D4 + (idx0 & 127u));
        v0.x += p.x; v0.y += p.y; v0.z += p.z; v0.w += p.w;
    }
    if (r1 >= 0) {
        const float4 p = __ldg(pe + (unsigned)r1 * D4 + (idx1 & 127u));
        v1.x += p.x; v1.y += p.y; v1.z += p.z; v1.w += p.w;
    }

    __stcs(out + idx0, v0);
    __stcs(out + idx1, v1);
}

// ---------------------------------------------------------------------------
// Launch.
// Inputs (metadata order): seqs [B,S,D] f32, masks [B,S] int32, pe [2048,D] f32
// Output: [B,S,D] f32
// ---------------------------------------------------------------------------
extern "C" void kernel_launch(void* const* d_in, const int* in_sizes, int n_in,
                              void* d_out, int out_size)
{
    const float* seqs  = (const float*)d_in[0];
    const int*   masks = (const int*)d_in[1];
    const float* pe    = (const float*)d_in[2];
    float*       out   = (float*)d_out;

    (void)in_sizes; (void)n_in; (void)out_size;

    rank_scan_kernel<<<PB, 1024>>>(masks);

    const unsigned total4 = (unsigned)PB * PS * D4;   // 8,388,608
    pe_add_kernel<<<total4 / 1024, 512>>>(
        (const float4*)seqs, (const float4*)pe, (float4*)out);
}

// round 7
// speedup vs baseline: 1.0119x; 1.0056x over previous
#include <cuda_runtime.h>
#include <cstdint>

// Problem constants (fixed by reference: B=32, S=2048, D=512)
#define PB 32
#define PS 2048
#define D4 128              // float4 per (b,s) position

// Scratch: rank per (b,s). rank >= 0 iff mask set; -1 otherwise.
__device__ int g_rank[PB * PS];

// ---------------------------------------------------------------------------
// Kernel 1: per-row rank via ballot/popc scan.
// One block (1024 threads = 32 warps) per row; two passes of 1024 positions.
// Pass i: thread t handles position t + i*1024. Warp counts via ballot+popc,
// block offsets via a single warp scanning the 64 warp counts.
// ---------------------------------------------------------------------------
__global__ void __launch_bounds__(1024, 1)
rank_scan_kernel(const int* __restrict__ masks)
{
    const int b = blockIdx.x;
    const int* m = masks + (size_t)b * PS;
    int*       r = g_rank + (size_t)b * PS;

    const int t    = threadIdx.x;
    const int lane = t & 31;
    const int w    = t >> 5;                 // 0..31

    __shared__ int warp_cnt[64];             // counts for 64 warp-chunks
    __shared__ int warp_off[64];             // exclusive offsets

    // Load both positions, ballot both passes
    const int p0 = t;
    const int p1 = t + 1024;
    const int m0 = (m[p0] != 0);
    const int m1 = (m[p1] != 0);

    const unsigned bal0 = __ballot_sync(0xFFFFFFFFu, m0);
    const unsigned bal1 = __ballot_sync(0xFFFFFFFFu, m1);

    if (lane == 0) {
        warp_cnt[w]      = __popc(bal0);
        warp_cnt[w + 32] = __popc(bal1);
    }
    __syncthreads();

    // Warp 0 scans the 64 warp counts -> exclusive offsets
    if (w == 0) {
        const int c0 = warp_cnt[lane];
        const int c1 = warp_cnt[lane + 32];

        int incl = c0;
        #pragma unroll
        for (int off = 1; off < 32; off <<= 1) {
            int v = __shfl_up_sync(0xFFFFFFFFu, incl, off);
            if (lane >= off) incl += v;
        }
        const int total0 = __shfl_sync(0xFFFFFFFFu, incl, 31);
        warp_off[lane] = incl - c0;

        int incl1 = c1;
        #pragma unroll
        for (int off = 1; off < 32; off <<= 1) {
            int v = __shfl_up_sync(0xFFFFFFFFu, incl1, off);
            if (lane >= off) incl1 += v;
        }
        warp_off[lane + 32] = total0 + incl1 - c1;
    }
    __syncthreads();

    const unsigned lt = (1u << lane) - 1u;
    const int rank0 = warp_off[w]      + __popc(bal0 & lt);
    const int rank1 = warp_off[w + 32] + __popc(bal1 & lt);

    r[p0] = m0 ? rank0 : -1;
    r[p1] = m1 ? rank1 : -1;
}

// ---------------------------------------------------------------------------
// Kernel 2 (R4 measured-best config): out = seqs + (rank >= 0 ? pe[rank] : 0).
// 256 threads/block, 2 float4 per thread, front-batched loads; __ldcs/__stcs
// keep the 256 MiB streaming traffic from evicting the 4 MiB pe table in L2.
// ---------------------------------------------------------------------------
__global__ void __launch_bounds__(256, 8)
pe_add_kernel(const float4* __restrict__ seqs,
              const float4* __restrict__ pe,
              float4*       __restrict__ out)
{
    const unsigned t    = threadIdx.x;
    const unsigned idx0 = blockIdx.x * 512u + t;       // element 0
    const unsigned idx1 = idx0 + 256u;                 // element 1

    const unsigned row0 = idx0 >> 7;
    const unsigned row1 = idx1 >> 7;
    const unsigned col0 = idx0 & 127u;
    const unsigned col1 = idx1 & 127u;

    // Front-batch all independent loads
    const int r0 = __ldg(&g_rank[row0]);
    const int r1 = __ldg(&g_rank[row1]);
    float4 v0 = __ldcs(seqs + idx0);
    float4 v1 = __ldcs(seqs + idx1);

    if (r0 >= 0) {
        const float4 p = __ldg(pe + (unsigned)r0 * D4 + col0);
        v0.x += p.x; v0.y += p.y; v0.z += p.z; v0.w += p.w;
    }
    if (r1 >= 0) {
        const float4 p = __ldg(pe + (unsigned)r1 * D4 + col1);
        v1.x += p.x; v1.y += p.y; v1.z += p.z; v1.w += p.w;
    }

    __stcs(out + idx0, v0);
    __stcs(out + idx1, v1);
}

// ---------------------------------------------------------------------------
// Launch.
// Inputs (metadata order): seqs [B,S,D] f32, masks [B,S] int32, pe [2048,D] f32
// Output: [B,S,D] f32
// ---------------------------------------------------------------------------
extern "C" void kernel_launch(void* const* d_in, const int* in_sizes, int n_in,
                              void* d_out, int out_size)
{
    const float* seqs  = (const float*)d_in[0];
    const int*   masks = (const int*)d_in[1];
    const float* pe    = (const float*)d_in[2];
    float*       out   = (float*)d_out;

    (void)in_sizes; (void)n_in; (void)out_size;

    rank_scan_kernel<<<PB, 1024>>>(masks);

    const unsigned total4 = (unsigned)PB * PS * D4;    // 8,388,608
    pe_add_kernel<<<total4 / 512, 256>>>(
        (const float4*)seqs, (const float4*)pe, (float4*)out);
}